// round 16
// baseline (speedup 1.0000x reference)
#include <cuda_runtime.h>
#include <cuda_bf16.h>
#include <cuda_fp16.h>
#include <cstdint>

#define NMAX 100000
#define EMAX 1600000
#define NF 18

// helper: reinterpret u32 bits as __half2
__device__ __forceinline__ __half2 u32_as_half2(unsigned u) {
    __half2 h;
    *reinterpret_cast<unsigned*>(&h) = u;
    return h;
}

__device__ __forceinline__ void ldsm_x4(uint32_t& r0, uint32_t& r1, uint32_t& r2,
                                        uint32_t& r3, uint32_t addr) {
    asm volatile("ldmatrix.sync.aligned.m8n8.x4.shared.b16 {%0,%1,%2,%3}, [%4];"
                 : "=r"(r0), "=r"(r1), "=r"(r2), "=r"(r3)
                 : "r"(addr));
}
__device__ __forceinline__ void ldsm_x2(uint32_t& r0, uint32_t& r1, uint32_t addr) {
    asm volatile("ldmatrix.sync.aligned.m8n8.x2.shared.b16 {%0,%1}, [%2];"
                 : "=r"(r0), "=r"(r1)
                 : "r"(addr));
}
__device__ __forceinline__ void mma16816(float& c0, float& c1, float& c2, float& c3,
                                         uint32_t a0, uint32_t a1, uint32_t a2,
                                         uint32_t a3, uint32_t b0, uint32_t b1) {
    asm volatile(
        "mma.sync.aligned.m16n8k16.row.col.f32.f16.f16.f32 "
        "{%0,%1,%2,%3}, {%4,%5,%6,%7}, {%8,%9}, {%0,%1,%2,%3};"
        : "+f"(c0), "+f"(c1), "+f"(c2), "+f"(c3)
        : "r"(a0), "r"(a1), "r"(a2), "r"(a3), "r"(b0), "r"(b1));
}

// ---------------- scratch (device globals; no allocations allowed) ----------
__device__ __align__(128) float g_x[NMAX * 64];
__device__ __align__(128) __half g_xh[NMAX * 64];   // fp16 shadow of x
__device__ __align__(256) __half g_PR[NMAX * 128];  // [msg 64 | att 32 | pad 32]
__device__ __align__(256) __half g_PC[NMAX * 128];  // [msg 64 | att 32 | pad 32]
__device__ __align__(128) float g_S[NMAX * 64];     // segment_sum(fw * h1)
__device__ __align__(128) float g_sumfw[NMAX];
__device__ __align__(128) float g_mx[64];
__device__ __align__(128) float g_Wc[2 * 4096];     // msgW2 @ updW1b per layer
__device__ __align__(128) float g_bvec[2 * 64];     // msgb2 @ updW1b per layer
__device__ __align__(128) __half g_Wb[2 * 192 * 64];// fused pre-weights, [n][k] fp16
__device__ __align__(128) float g_bias[2 * 192];    // fused pre-bias (0 for PC)
__device__ __align__(128) __half g_Wu[2 * 3 * 4096];// update weights [n][k] fp16: Wc|U1a|U2
// counting-sort (by destination col) scratch
__device__ __align__(128) int g_cnt[NMAX];
__device__ __align__(128) int g_fill[NMAX];
__device__ __align__(128) int4 g_epack[EMAX];       // {row, col, weight-bits, 0} sorted by col

// ---------------- sort build: zero counts, histogram, scan, scatter ---------
__global__ void k_czero(int n) {
    int i = blockIdx.x * blockDim.x + threadIdx.x;
    int st = gridDim.x * blockDim.x;
    for (; i < n; i += st) g_cnt[i] = 0;
}

__global__ void k_hist(const int* __restrict__ col, int ne) {
    int i = blockIdx.x * blockDim.x + threadIdx.x;
    int st = gridDim.x * blockDim.x;
    for (; i < ne; i += st) atomicAdd(&g_cnt[col[i]], 1);
}

__global__ void k_scan(int n) {  // single block, 1024 threads
    __shared__ int ss[1024];
    int t = threadIdx.x;
    int chunk = (n + 1023) >> 10;
    int st = t * chunk, en = min(st + chunk, n);
    int s = 0;
    for (int i = st; i < en; i++) s += g_cnt[i];
    ss[t] = s;
    __syncthreads();
#pragma unroll
    for (int o = 1; o < 1024; o <<= 1) {
        int v = (t >= o) ? ss[t - o] : 0;
        __syncthreads();
        ss[t] += v;
        __syncthreads();
    }
    int run = (t > 0) ? ss[t - 1] : 0;
    for (int i = st; i < en; i++) {
        g_fill[i] = run;
        run += g_cnt[i];
    }
}

__global__ void k_scatter(const int* __restrict__ row, const int* __restrict__ col,
                          const float* __restrict__ ew, int ne) {
    int i = blockIdx.x * blockDim.x + threadIdx.x;
    int st = gridDim.x * blockDim.x;
    for (; i < ne; i += st) {
        int c = col[i];
        int p = atomicAdd(&g_fill[c], 1);
        g_epack[p] = make_int4(row[i], c, __float_as_int(ew[i]), 0);
    }
}

// ---------------- k_wprep: build fused fp16 pre-weight [n][k] + bias --------
__global__ __launch_bounds__(256) void k_wprep(const float* __restrict__ mW1,
                                               const float* __restrict__ aW1,
                                               const float* __restrict__ mb1,
                                               const float* __restrict__ ab1) {
    int l = blockIdx.x;
    int tid = threadIdx.x;
    const float* mW = mW1 + l * 8192;
    const float* aW = aW1 + l * 4096;
    for (int idx = tid; idx < 192 * 64; idx += 256) {
        int nn = idx >> 6, k = idx & 63;
        float v;
        if (nn < 64) v = mW[k * 64 + nn];
        else if (nn < 128) v = mW[(64 + k) * 64 + (nn - 64)];
        else if (nn < 160) v = aW[k * 32 + (nn - 128)];
        else v = aW[(64 + k) * 32 + (nn - 160)];
        g_Wb[l * 12288 + idx] = __float2half_rn(v);
    }
    for (int nn = tid; nn < 192; nn += 256) {
        float b = 0.f;
        if (nn < 64) b = mb1[l * 64 + nn];
        else if (nn >= 128 && nn < 160) b = ab1[l * 32 + (nn - 128)];
        g_bias[l * 192 + nn] = b;
    }
}

// ---------------- k_fuse: Wc = msgW2 @ updW1[64:128], bvec = msgb2 @ updW1b -
__global__ __launch_bounds__(256) void k_fuse(const float* __restrict__ msgW2,
                                              const float* __restrict__ msgB2,
                                              const float* __restrict__ updW1) {
    int l = blockIdx.x, chunk = blockIdx.y;
    __shared__ float sU1b[4096];
    const float* U1b = updW1 + l * 8192 + 4096;
    int tid = threadIdx.x;
    for (int i = tid; i < 4096; i += 256) sU1b[i] = U1b[i];
    __syncthreads();
    const float* W2 = msgW2 + l * 4096;
    int i0 = chunk * 8 + (tid >> 5);
    int o = tid & 31;
    float acc0 = 0.f, acc1 = 0.f;
#pragma unroll 8
    for (int j = 0; j < 64; j++) {
        float w = __ldg(&W2[i0 * 64 + j]);
        acc0 += w * sU1b[j * 64 + o];
        acc1 += w * sU1b[j * 64 + o + 32];
    }
    g_Wc[l * 4096 + i0 * 64 + o] = acc0;
    g_Wc[l * 4096 + i0 * 64 + o + 32] = acc1;
    if (chunk == 0 && tid < 64) {
        float acc = 0.f;
        const float* b2 = msgB2 + l * 64;
#pragma unroll 8
        for (int j = 0; j < 64; j++) acc += __ldg(&b2[j]) * sU1b[j * 64 + tid];
        g_bvec[l * 64 + tid] = acc;
    }
}

// ---------------- k_wprep2: update weights -> fp16 [n][k] (Wc | U1a | U2) ---
__global__ __launch_bounds__(256) void k_wprep2(const float* __restrict__ updW1,
                                                const float* __restrict__ updW2) {
    int l = blockIdx.x;
    int tid = threadIdx.x;
    for (int idx = tid; idx < 3 * 4096; idx += 256) {
        int part = idx >> 12;
        int rem = idx & 4095;
        int nn = rem >> 6, k = rem & 63;
        float v;
        if (part == 0) v = g_Wc[l * 4096 + k * 64 + nn];
        else if (part == 1) v = updW1[l * 8192 + k * 64 + nn];
        else v = updW2[l * 4096 + k * 64 + nn];
        g_Wu[l * 12288 + idx] = __float2half_rn(v);
    }
}

// ---------------- embed: x = relu(nf @ W + b) + zero S/sumfw/mx -------------
__global__ __launch_bounds__(256) void k_embed(const float* __restrict__ nf,
                                               const float* __restrict__ W,
                                               const float* __restrict__ b, int n) {
    __shared__ float sW[NF * 64];
    __shared__ float sb[64];
    int tid = threadIdx.x;
    for (int i = tid; i < NF * 64; i += blockDim.x) sW[i] = W[i];
    if (tid < 64) sb[tid] = b[tid];
    __syncthreads();
    int gtid = blockIdx.x * blockDim.x + tid;
    int gstr = gridDim.x * blockDim.x;
    float4 z4 = make_float4(0.f, 0.f, 0.f, 0.f);
    int q = n * 16;
    for (int i = gtid; i < q; i += gstr) reinterpret_cast<float4*>(g_S)[i] = z4;
    for (int i = gtid; i < n; i += gstr) g_sumfw[i] = 0.f;
    if (gtid < 64) g_mx[gtid] = 0.f;

    int warp = tid >> 5, lane = tid & 31;
    for (int node = blockIdx.x * 8 + warp; node < n; node += gridDim.x * 8) {
        float v = (lane < NF) ? nf[(long)node * NF + lane] : 0.f;
        float a0 = sb[2 * lane], a1 = sb[2 * lane + 1];
#pragma unroll
        for (int k = 0; k < NF; k++) {
            float xv = __shfl_sync(0xffffffffu, v, k);
            a0 += xv * sW[k * 64 + 2 * lane];
            a1 += xv * sW[k * 64 + 2 * lane + 1];
        }
        float2 r;
        r.x = fmaxf(a0, 0.f);
        r.y = fmaxf(a1, 0.f);
        *reinterpret_cast<float2*>(&g_x[(size_t)node * 64 + 2 * lane]) = r;
        *reinterpret_cast<__half2*>(&g_xh[(size_t)node * 64 + 2 * lane]) =
            __floats2half2_rn(r.x, r.y);
    }
}

// ---------------- k_pre_mma: PR/PC via tensor cores -------------------------
__global__ __launch_bounds__(256) void k_pre_mma(int l, int n) {
    extern __shared__ __align__(16) unsigned char smraw[];
    __half* sWb = reinterpret_cast<__half*>(smraw);                 // 192*64 halfs
    __half* sx = reinterpret_cast<__half*>(smraw + 24576);          // 128*64 halfs
    float* sbias = reinterpret_cast<float*>(smraw + 24576 + 16384); // 192 floats
    int tid = threadIdx.x;
    const uint4* gW = reinterpret_cast<const uint4*>(g_Wb + l * 12288);
    uint4* sW4 = reinterpret_cast<uint4*>(sWb);
    for (int i = tid; i < 1536; i += 256) {
        int r = i >> 3, c = i & 7;
        sW4[r * 8 + (c ^ (r & 7))] = gW[i];
    }
    for (int i = tid; i < 192; i += 256) sbias[i] = g_bias[l * 192 + i];
    uint32_t sx_u = (uint32_t)__cvta_generic_to_shared(sx);
    uint32_t sW_u = (uint32_t)__cvta_generic_to_shared(sWb);
    int warp = tid >> 5, lane = tid & 31;
    int nb = (n + 127) >> 7;

    for (int batch = blockIdx.x; batch < nb; batch += gridDim.x) {
        int base = batch << 7;
        __syncthreads();
        const uint4* gx = reinterpret_cast<const uint4*>(g_xh + (size_t)base * 64);
        uint4* sx4 = reinterpret_cast<uint4*>(sx);
        for (int i = tid; i < 1024; i += 256) {
            int r = i >> 3, c = i & 7;
            uint4 v = make_uint4(0, 0, 0, 0);
            if (base + r < n) v = gx[i];
            sx4[r * 8 + (c ^ (r & 7))] = v;
        }
        __syncthreads();

        uint32_t a[4][4];
        int m0 = warp * 16;
        {
            int grp = lane >> 3, lr = lane & 7;
            int r = m0 + ((grp & 1) << 3) + lr;
            int chalf = grp >> 1;
#pragma unroll
            for (int kb = 0; kb < 4; kb++) {
                int c = kb * 2 + chalf;
                uint32_t addr = sx_u + (uint32_t)((r * 8 + (c ^ (r & 7))) * 16);
                ldsm_x4(a[kb][0], a[kb][1], a[kb][2], a[kb][3], addr);
            }
        }
        int grp2 = (lane >> 3) & 1, lr2 = lane & 7;
        int mlo = base + m0 + (lane >> 2);
        int mhi = mlo + 8;
#pragma unroll 1
        for (int t = 0; t < 24; t++) {
            float c0 = 0.f, c1 = 0.f, c2 = 0.f, c3 = 0.f;
#pragma unroll
            for (int kb = 0; kb < 4; kb++) {
                int nrow = t * 8 + lr2;
                int cch = kb * 2 + grp2;
                uint32_t baddr =
                    sW_u + (uint32_t)((nrow * 8 + (cch ^ (nrow & 7))) * 16);
                uint32_t b0, b1;
                ldsm_x2(b0, b1, baddr);
                mma16816(c0, c1, c2, c3, a[kb][0], a[kb][1], a[kb][2], a[kb][3],
                         b0, b1);
            }
            int nloc = t * 8 + 2 * (lane & 3);
            float bsa = sbias[nloc], bsb = sbias[nloc + 1];
            c0 += bsa; c1 += bsb; c2 += bsa; c3 += bsb;
            __half* dst;
            int off;
            if (t < 8) { dst = g_PR; off = nloc; }
            else if (t < 16) { dst = g_PC; off = nloc - 64; }
            else if (t < 20) { dst = g_PR; off = nloc - 64; }
            else { dst = g_PC; off = nloc - 96; }
            if (mlo < n)
                *reinterpret_cast<__half2*>(dst + (size_t)mlo * 128 + off) =
                    __floats2half2_rn(c0, c1);
            if (mhi < n)
                *reinterpret_cast<__half2*>(dst + (size_t)mhi * 128 + off) =
                    __floats2half2_rn(c2, c3);
        }
    }
}

// ---------------- k_edge_sorted: half-warp per contiguous sorted chunk ------
// Edges sorted by col: PC partials and S accumulator live in registers for
// each col-run; one red.v4 flush per run boundary.
__global__ __launch_bounds__(128) void k_edge_sorted(const float* __restrict__ aW2,
                                                     const float* __restrict__ ab2,
                                                     int ne) {
    int tid = threadIdx.x;
    int warp = tid >> 5;
    int half = (tid >> 4) & 1;
    int hl = tid & 15;
    int HW = gridDim.x * 8;
    int C = (ne + HW - 1) / HW;
    int hw0 = blockIdx.x * 8 + 2 * warp;  // first halfwarp of this warp
    if ((long)hw0 * C >= ne) return;      // warp-uniform early out
    int hw = hw0 + half;
    int e0 = hw * C;
    int e1 = min(e0 + C, ne);
    float2 aw;
    aw.x = __ldg(aW2 + 2 * hl);
    aw.y = __ldg(aW2 + 2 * hl + 1);
    float ab2v = __ldg(ab2);
    const __half2 z2 = __float2half2_rn(0.f);

    int cur = -1;
    float ax0 = 0.f, ax1 = 0.f, ax2 = 0.f, ax3 = 0.f, sfw = 0.f;
    __half2 pmc0 = z2, pmc1 = z2, pac = z2;

    for (int i = 0; i < C; i++) {
        int e = e0 + i;
        bool valid = e < e1;
        int ec = valid ? e : (ne - 1);
        int4 pk = __ldg(&g_epack[ec]);
        int r = pk.x, c = pk.y;
        float w = valid ? __int_as_float(pk.z) : 0.f;
        if (c != cur) {
            if (cur >= 0) {
                float* d = &g_S[(size_t)cur * 64 + 4 * hl];
                asm volatile("red.global.add.v4.f32 [%0], {%1,%2,%3,%4};" ::"l"(d),
                             "f"(ax0), "f"(ax1), "f"(ax2), "f"(ax3)
                             : "memory");
                if (hl == 0) atomicAdd(&g_sumfw[cur], sfw);
            }
            cur = c;
            ax0 = ax1 = ax2 = ax3 = 0.f;
            sfw = 0.f;
            const __half* pc = g_PC + (size_t)c * 128;
            uint2 t2 = __ldg(reinterpret_cast<const uint2*>(pc + 4 * hl));
            pmc0 = u32_as_half2(t2.x);
            pmc1 = u32_as_half2(t2.y);
            pac = __ldg(reinterpret_cast<const __half2*>(pc + 64 + 2 * hl));
        }
        const __half* pr = g_PR + (size_t)r * 128;
        uint2 pm = __ldg(reinterpret_cast<const uint2*>(pr + 4 * hl));
        __half2 par = __ldg(reinterpret_cast<const __half2*>(pr + 64 + 2 * hl));
        float2 af = __half22float2(__hmax2(__hadd2(par, pac), z2));
        float t = af.x * aw.x + af.y * aw.y;
#pragma unroll
        for (int o = 8; o > 0; o >>= 1) t += __shfl_xor_sync(0xffffffffu, t, o);
        float fw = w / (1.f + __expf(-(t + ab2v)));
        float2 f0 = __half22float2(
            __hmax2(__hadd2(u32_as_half2(pm.x), pmc0), z2));
        float2 f1 = __half22float2(
            __hmax2(__hadd2(u32_as_half2(pm.y), pmc1), z2));
        ax0 += fw * f0.x;
        ax1 += fw * f0.y;
        ax2 += fw * f1.x;
        ax3 += fw * f1.y;
        sfw += fw;
    }
    if (cur >= 0) {
        float* d = &g_S[(size_t)cur * 64 + 4 * hl];
        asm volatile("red.global.add.v4.f32 [%0], {%1,%2,%3,%4};" ::"l"(d),
                     "f"(ax0), "f"(ax1), "f"(ax2), "f"(ax3)
                     : "memory");
        if (hl == 0) atomicAdd(&g_sumfw[cur], sfw);
    }
}

// ---------------- k_update_mma: tensor-core fused update (rezero fused) -----
// h = relu(b1 + inv*(S@Wc) + (sf*inv)*bvec + X@U1a); o = relu(h@U2 + b2 + x)
__global__ __launch_bounds__(256) void k_update_mma(int l,
                                                    const float* __restrict__ ub1,
                                                    const float* __restrict__ ub2,
                                                    int n, int do_max) {
    extern __shared__ __align__(16) unsigned char smraw[];
    __half* sW = reinterpret_cast<__half*>(smraw);          // 3*4096 halfs (24576B)
    __half* sx = reinterpret_cast<__half*>(smraw + 24576);  // 8192 halfs (16384B)
    __half* sh = reinterpret_cast<__half*>(smraw + 40960);  // S then H (16384B)
    float* sb = reinterpret_cast<float*>(smraw + 57344);    // 192: b1|b2|bvec
    float* ssf = sb + 192;                                  // 128
    unsigned* smx = reinterpret_cast<unsigned*>(ssf + 128); // 64
    int tid = threadIdx.x;

    {
        const uint4* gW = reinterpret_cast<const uint4*>(g_Wu + l * 12288);
        uint4* sW4 = reinterpret_cast<uint4*>(sW);
        for (int i = tid; i < 1536; i += 256) {
            int r = i >> 3, c = i & 7;
            sW4[r * 8 + (c ^ (r & 7))] = gW[i];
        }
        if (tid < 64) {
            sb[tid] = ub1[tid];
            sb[64 + tid] = ub2[tid];
            sb[128 + tid] = g_bvec[l * 64 + tid];
            smx[tid] = 0u;
        }
    }
    uint32_t sx_u = (uint32_t)__cvta_generic_to_shared(sx);
    uint32_t sh_u = (uint32_t)__cvta_generic_to_shared(sh);
    uint32_t sW_u = (uint32_t)__cvta_generic_to_shared(sW);
    int warp = tid >> 5, lane = tid & 31;
    int m0 = warp * 16;
    int grp = lane >> 3, lr = lane & 7;
    int afr = m0 + ((grp & 1) << 3) + lr;
    int achalf = grp >> 1;
    int grp2 = (lane >> 3) & 1, lr2 = lane & 7;
    int rlo = m0 + (lane >> 2), rhi = rlo + 8;
    int nb = (n + 127) >> 7;
    float mxa[8], mxb[8];
#pragma unroll
    for (int t = 0; t < 8; t++) { mxa[t] = 0.f; mxb[t] = 0.f; }
    float4 z4 = make_float4(0.f, 0.f, 0.f, 0.f);

    for (int batch = blockIdx.x; batch < nb; batch += gridDim.x) {
        int base = batch << 7;
        __syncthreads();
        {
            const uint4* gx = reinterpret_cast<const uint4*>(g_xh + (size_t)base * 64);
            uint4* sx4 = reinterpret_cast<uint4*>(sx);
            uint4* sh4 = reinterpret_cast<uint4*>(sh);
            float4* gs4 = reinterpret_cast<float4*>(g_S + (size_t)base * 64);
            for (int i = tid; i < 1024; i += 256) {
                int r = i >> 3;
                uint4 vx = make_uint4(0, 0, 0, 0);
                uint4 vs = make_uint4(0, 0, 0, 0);
                if (base + r < n) {
                    vx = gx[i];
                    float4 f0 = gs4[2 * i];
                    float4 f1 = gs4[2 * i + 1];
                    gs4[2 * i] = z4;          // rezero for next layer / replay
                    gs4[2 * i + 1] = z4;
                    __half2 h0 = __floats2half2_rn(f0.x, f0.y);
                    __half2 h1 = __floats2half2_rn(f0.z, f0.w);
                    __half2 h2 = __floats2half2_rn(f1.x, f1.y);
                    __half2 h3 = __floats2half2_rn(f1.z, f1.w);
                    vs.x = *reinterpret_cast<unsigned*>(&h0);
                    vs.y = *reinterpret_cast<unsigned*>(&h1);
                    vs.z = *reinterpret_cast<unsigned*>(&h2);
                    vs.w = *reinterpret_cast<unsigned*>(&h3);
                }
                int d = (i >> 3) * 8 + ((i & 7) ^ ((i >> 3) & 7));
                sx4[d] = vx;
                sh4[d] = vs;
            }
            if (tid < 128) {
                float sf = 1.f;
                if (base + tid < n) {
                    sf = g_sumfw[base + tid];
                    g_sumfw[base + tid] = 0.f;
                }
                ssf[tid] = sf;
            }
        }
        __syncthreads();

        uint32_t aS[4][4], aX[4][4];
#pragma unroll
        for (int kb = 0; kb < 4; kb++) {
            int c = kb * 2 + achalf;
            uint32_t off = (uint32_t)((afr * 8 + (c ^ (afr & 7))) * 16);
            ldsm_x4(aS[kb][0], aS[kb][1], aS[kb][2], aS[kb][3], sh_u + off);
            ldsm_x4(aX[kb][0], aX[kb][1], aX[kb][2], aX[kb][3], sx_u + off);
        }
        float sflo = ssf[rlo], sfhi = ssf[rhi];
        float invlo = 1.f / fmaxf(sflo, 1e-6f);
        float invhi = 1.f / fmaxf(sfhi, 1e-6f);
        float ratlo = sflo * invlo, rathi = sfhi * invhi;

#pragma unroll 1
        for (int t = 0; t < 8; t++) {
            float g0 = 0.f, g1 = 0.f, g2 = 0.f, g3 = 0.f;
            float h0 = 0.f, h1 = 0.f, h2 = 0.f, h3 = 0.f;
            int nrow = t * 8 + lr2;
#pragma unroll
            for (int kb = 0; kb < 4; kb++) {
                int cch = kb * 2 + grp2;
                uint32_t off = (uint32_t)((nrow * 8 + (cch ^ (nrow & 7))) * 16);
                uint32_t b0, b1;
                ldsm_x2(b0, b1, sW_u + off);
                mma16816(g0, g1, g2, g3, aS[kb][0], aS[kb][1], aS[kb][2], aS[kb][3], b0, b1);
                ldsm_x2(b0, b1, sW_u + 8192u + off);
                mma16816(h0, h1, h2, h3, aX[kb][0], aX[kb][1], aX[kb][2], aX[kb][3], b0, b1);
            }
            int nloc = t * 8 + 2 * (lane & 3);
            float b1a = sb[nloc], b1b = sb[nloc + 1];
            float bva = sb[128 + nloc], bvb = sb[128 + nloc + 1];
            float v0 = fmaxf(b1a + invlo * g0 + ratlo * bva + h0, 0.f);
            float v1 = fmaxf(b1b + invlo * g1 + ratlo * bvb + h1, 0.f);
            float v2 = fmaxf(b1a + invhi * g2 + rathi * bva + h2, 0.f);
            float v3 = fmaxf(b1b + invhi * g3 + rathi * bvb + h3, 0.f);
            *reinterpret_cast<__half2*>(
                sh + (size_t)((rlo * 8 + (t ^ (rlo & 7))) * 8 + 2 * (lane & 3))) =
                __floats2half2_rn(v0, v1);
            *reinterpret_cast<__half2*>(
                sh + (size_t)((rhi * 8 + (t ^ (rhi & 7))) * 8 + 2 * (lane & 3))) =
                __floats2half2_rn(v2, v3);
        }
        __syncwarp();

#pragma unroll
        for (int kb = 0; kb < 4; kb++) {
            int c = kb * 2 + achalf;
            uint32_t off = (uint32_t)((afr * 8 + (c ^ (afr & 7))) * 16);
            ldsm_x4(aS[kb][0], aS[kb][1], aS[kb][2], aS[kb][3], sh_u + off);
        }

        bool vlo = (base + rlo) < n, vhi = (base + rhi) < n;
#pragma unroll 1
        for (int t = 0; t < 8; t++) {
            float o0 = 0.f, o1 = 0.f, o2 = 0.f, o3 = 0.f;
            int nrow = t * 8 + lr2;
#pragma unroll
            for (int kb = 0; kb < 4; kb++) {
                int cch = kb * 2 + grp2;
                uint32_t off = (uint32_t)((nrow * 8 + (cch ^ (nrow & 7))) * 16);
                uint32_t b0, b1;
                ldsm_x2(b0, b1, sW_u + 16384u + off);
                mma16816(o0, o1, o2, o3, aS[kb][0], aS[kb][1], aS[kb][2], aS[kb][3], b0, b1);
            }
            int nloc = t * 8 + 2 * (lane & 3);
            float b2a = sb[64 + nloc], b2b = sb[64 + nloc + 1];
            float2 xlo = __half22float2(*reinterpret_cast<const __half2*>(
                sx + (size_t)((rlo * 8 + (t ^ (rlo & 7))) * 8 + 2 * (lane & 3))));
            float2 xhi = __half22float2(*reinterpret_cast<const __half2*>(
                sx + (size_t)((rhi * 8 + (t ^ (rhi & 7))) * 8 + 2 * (lane & 3))));
            float r0 = fmaxf(o0 + b2a + xlo.x, 0.f);
            float r1 = fmaxf(o1 + b2b + xlo.y, 0.f);
            float r2 = fmaxf(o2 + b2a + xhi.x, 0.f);
            float r3 = fmaxf(o3 + b2b + xhi.y, 0.f);
            if (vlo) {
                float2 t2; t2.x = r0; t2.y = r1;
                *reinterpret_cast<float2*>(&g_x[(size_t)(base + rlo) * 64 + nloc]) = t2;
                *reinterpret_cast<__half2*>(&g_xh[(size_t)(base + rlo) * 64 + nloc]) =
                    __floats2half2_rn(r0, r1);
                mxa[t] = fmaxf(mxa[t], r0);
                mxb[t] = fmaxf(mxb[t], r1);
            }
            if (vhi) {
                float2 t2; t2.x = r2; t2.y = r3;
                *reinterpret_cast<float2*>(&g_x[(size_t)(base + rhi) * 64 + nloc]) = t2;
                *reinterpret_cast<__half2*>(&g_xh[(size_t)(base + rhi) * 64 + nloc]) =
                    __floats2half2_rn(r2, r3);
                mxa[t] = fmaxf(mxa[t], r2);
                mxb[t] = fmaxf(mxb[t], r3);
            }
        }
    }

    if (do_max) {
        __syncthreads();
#pragma unroll
        for (int t = 0; t < 8; t++) {
            int nloc = t * 8 + 2 * (lane & 3);
            atomicMax(&smx[nloc], __float_as_uint(mxa[t]));
            atomicMax(&smx[nloc + 1], __float_as_uint(mxb[t]));
        }
        __syncthreads();
        if (tid < 64)
            atomicMax(reinterpret_cast<unsigned*>(&g_mx[tid]), smx[tid]);
    }
}

// ---------------- head: out = max_x @ head_W + head_b -----------------------
__global__ void k_head(const float* __restrict__ hW, const float* __restrict__ hb,
                       float* __restrict__ out) {
    int t = threadIdx.x;
    float v = g_mx[t] * hW[t];
#pragma unroll
    for (int o = 16; o > 0; o >>= 1) v += __shfl_xor_sync(0xffffffffu, v, o);
    __shared__ float s[2];
    if ((t & 31) == 0) s[t >> 5] = v;
    __syncthreads();
    if (t == 0) out[0] = s[0] + s[1] + hb[0];
}

// ---------------- launch ----------------------------------------------------
extern "C" void kernel_launch(void* const* d_in, const int* in_sizes, int n_in,
                              void* d_out, int out_size) {
    const float* nf = (const float*)d_in[0];
    const int* ei = (const int*)d_in[1];
    const float* ew = (const float*)d_in[2];
    const float* embW = (const float*)d_in[3];
    const float* embB = (const float*)d_in[4];
    const float* msgW1 = (const float*)d_in[5];
    const float* msgB1 = (const float*)d_in[6];
    const float* msgW2 = (const float*)d_in[7];
    const float* msgB2 = (const float*)d_in[8];
    const float* attW1 = (const float*)d_in[9];
    const float* attB1 = (const float*)d_in[10];
    const float* attW2 = (const float*)d_in[11];
    const float* attB2 = (const float*)d_in[12];
    const float* updW1 = (const float*)d_in[13];
    const float* updB1 = (const float*)d_in[14];
    const float* updW2 = (const float*)d_in[15];
    const float* updB2 = (const float*)d_in[16];
    const float* headW = (const float*)d_in[17];
    const float* headB = (const float*)d_in[18];
    float* out = (float*)d_out;

    int n = in_sizes[0] / NF;
    int ne = in_sizes[2];
    const int* row = ei;
    const int* col = ei + ne;

    cudaFuncSetAttribute(k_pre_mma, cudaFuncAttributeMaxDynamicSharedMemorySize, 41728);
    cudaFuncSetAttribute(k_update_mma, cudaFuncAttributeMaxDynamicSharedMemorySize, 59904);

    // counting sort by destination col (once; reused by both layers)
    k_czero<<<128, 512>>>(n);
    k_hist<<<1184, 256>>>(col, ne);
    k_scan<<<1, 1024>>>(n);
    k_scatter<<<1184, 256>>>(row, col, ew, ne);
    // weight prep + embed
    k_wprep<<<2, 256>>>(msgW1, attW1, msgB1, attB1);
    k_fuse<<<dim3(2, 8), 256>>>(msgW2, msgB2, updW1);
    k_wprep2<<<2, 256>>>(updW1, updW2);
    k_embed<<<1184, 256>>>(nf, embW, embB, n);
    for (int l = 0; l < 2; l++) {
        k_pre_mma<<<296, 256, 41728>>>(l, n);
        k_edge_sorted<<<2368, 128>>>(attW2 + l * 32, attB2 + l, ne);
        k_update_mma<<<444, 256, 59904>>>(l, updB1 + l * 64, updB2 + l * 64, n,
                                          (l == 1) ? 1 : 0);
    }
    k_head<<<1, 64>>>(headW, headB, out);
}

// round 17
// speedup vs baseline: 1.2943x; 1.2943x over previous
#include <cuda_runtime.h>
#include <cuda_bf16.h>
#include <cuda_fp16.h>
#include <cstdint>

#define NMAX 100000
#define NF 18

// helper: reinterpret u32 bits as __half2
__device__ __forceinline__ __half2 u32_as_half2(unsigned u) {
    __half2 h;
    *reinterpret_cast<unsigned*>(&h) = u;
    return h;
}

__device__ __forceinline__ void ldsm_x4(uint32_t& r0, uint32_t& r1, uint32_t& r2,
                                        uint32_t& r3, uint32_t addr) {
    asm volatile("ldmatrix.sync.aligned.m8n8.x4.shared.b16 {%0,%1,%2,%3}, [%4];"
                 : "=r"(r0), "=r"(r1), "=r"(r2), "=r"(r3)
                 : "r"(addr));
}
__device__ __forceinline__ void ldsm_x2(uint32_t& r0, uint32_t& r1, uint32_t addr) {
    asm volatile("ldmatrix.sync.aligned.m8n8.x2.shared.b16 {%0,%1}, [%2];"
                 : "=r"(r0), "=r"(r1)
                 : "r"(addr));
}
__device__ __forceinline__ void mma16816(float& c0, float& c1, float& c2, float& c3,
                                         uint32_t a0, uint32_t a1, uint32_t a2,
                                         uint32_t a3, uint32_t b0, uint32_t b1) {
    asm volatile(
        "mma.sync.aligned.m16n8k16.row.col.f32.f16.f16.f32 "
        "{%0,%1,%2,%3}, {%4,%5,%6,%7}, {%8,%9}, {%0,%1,%2,%3};"
        : "+f"(c0), "+f"(c1), "+f"(c2), "+f"(c3)
        : "r"(a0), "r"(a1), "r"(a2), "r"(a3), "r"(b0), "r"(b1));
}

// ---------------- scratch (device globals; no allocations allowed) ----------
__device__ __align__(128) float g_x[NMAX * 64];
__device__ __align__(128) __half g_xh[NMAX * 64];   // fp16 shadow of x
__device__ __align__(256) __half g_PR[NMAX * 128];  // [msg 64 | att 32 | pad 32]
__device__ __align__(256) __half g_PC[NMAX * 128];  // [msg 64 | att 32 | pad 32]
__device__ __align__(128) float g_S[NMAX * 64];     // segment_sum(fw * h1)
__device__ __align__(128) float g_sumfw[NMAX];
__device__ __align__(128) float g_mx[64];
__device__ __align__(128) float g_Wc[2 * 4096];     // msgW2 @ updW1b per layer
__device__ __align__(128) float g_bvec[2 * 64];     // msgb2 @ updW1b per layer
__device__ __align__(128) __half g_Wb[2 * 192 * 64];// fused pre-weights, [n][k] fp16
__device__ __align__(128) float g_bias[2 * 192];    // fused pre-bias (0 for PC)
__device__ __align__(128) __half g_Wu[2 * 3 * 4096];// update weights [n][k] fp16: Wc|U1a|U2

// ---------------- k_wprep: build fused fp16 pre-weight [n][k] + bias --------
__global__ __launch_bounds__(256) void k_wprep(const float* __restrict__ mW1,
                                               const float* __restrict__ aW1,
                                               const float* __restrict__ mb1,
                                               const float* __restrict__ ab1) {
    int l = blockIdx.x;
    int tid = threadIdx.x;
    const float* mW = mW1 + l * 8192;
    const float* aW = aW1 + l * 4096;
    for (int idx = tid; idx < 192 * 64; idx += 256) {
        int nn = idx >> 6, k = idx & 63;
        float v;
        if (nn < 64) v = mW[k * 64 + nn];
        else if (nn < 128) v = mW[(64 + k) * 64 + (nn - 64)];
        else if (nn < 160) v = aW[k * 32 + (nn - 128)];
        else v = aW[(64 + k) * 32 + (nn - 160)];
        g_Wb[l * 12288 + idx] = __float2half_rn(v);
    }
    for (int nn = tid; nn < 192; nn += 256) {
        float b = 0.f;
        if (nn < 64) b = mb1[l * 64 + nn];
        else if (nn >= 128 && nn < 160) b = ab1[l * 32 + (nn - 128)];
        g_bias[l * 192 + nn] = b;
    }
}

// ---------------- k_fuse: Wc = msgW2 @ updW1[64:128], bvec = msgb2 @ updW1b -
__global__ __launch_bounds__(256) void k_fuse(const float* __restrict__ msgW2,
                                              const float* __restrict__ msgB2,
                                              const float* __restrict__ updW1) {
    int l = blockIdx.x, chunk = blockIdx.y;
    __shared__ float sU1b[4096];
    const float* U1b = updW1 + l * 8192 + 4096;
    int tid = threadIdx.x;
    for (int i = tid; i < 4096; i += 256) sU1b[i] = U1b[i];
    __syncthreads();
    const float* W2 = msgW2 + l * 4096;
    int i0 = chunk * 8 + (tid >> 5);
    int o = tid & 31;
    float acc0 = 0.f, acc1 = 0.f;
#pragma unroll 8
    for (int j = 0; j < 64; j++) {
        float w = __ldg(&W2[i0 * 64 + j]);
        acc0 += w * sU1b[j * 64 + o];
        acc1 += w * sU1b[j * 64 + o + 32];
    }
    g_Wc[l * 4096 + i0 * 64 + o] = acc0;
    g_Wc[l * 4096 + i0 * 64 + o + 32] = acc1;
    if (chunk == 0 && tid < 64) {
        float acc = 0.f;
        const float* b2 = msgB2 + l * 64;
#pragma unroll 8
        for (int j = 0; j < 64; j++) acc += __ldg(&b2[j]) * sU1b[j * 64 + tid];
        g_bvec[l * 64 + tid] = acc;
    }
}

// ---------------- k_wprep2: update weights -> fp16 [n][k] (Wc | U1a | U2) ---
__global__ __launch_bounds__(256) void k_wprep2(const float* __restrict__ updW1,
                                                const float* __restrict__ updW2) {
    int l = blockIdx.x;
    int tid = threadIdx.x;
    for (int idx = tid; idx < 3 * 4096; idx += 256) {
        int part = idx >> 12;
        int rem = idx & 4095;
        int nn = rem >> 6, k = rem & 63;
        float v;
        if (part == 0) v = g_Wc[l * 4096 + k * 64 + nn];
        else if (part == 1) v = updW1[l * 8192 + k * 64 + nn];
        else v = updW2[l * 4096 + k * 64 + nn];
        g_Wu[l * 12288 + idx] = __float2half_rn(v);
    }
}

// ---------------- embed: x = relu(nf @ W + b) + zero S/sumfw/mx -------------
// software-pipelined node loop (prefetch next node's features)
__global__ __launch_bounds__(256) void k_embed(const float* __restrict__ nf,
                                               const float* __restrict__ W,
                                               const float* __restrict__ b, int n) {
    __shared__ float sW[NF * 64];
    __shared__ float sb[64];
    int tid = threadIdx.x;
    for (int i = tid; i < NF * 64; i += blockDim.x) sW[i] = W[i];
    if (tid < 64) sb[tid] = b[tid];
    __syncthreads();
    int gtid = blockIdx.x * blockDim.x + tid;
    int gstr = gridDim.x * blockDim.x;
    float4 z4 = make_float4(0.f, 0.f, 0.f, 0.f);
    int q = n * 16;
    for (int i = gtid; i < q; i += gstr) reinterpret_cast<float4*>(g_S)[i] = z4;
    for (int i = gtid; i < n; i += gstr) g_sumfw[i] = 0.f;
    if (gtid < 64) g_mx[gtid] = 0.f;

    int warp = tid >> 5, lane = tid & 31;
    int stride = gridDim.x * 8;
    int node = blockIdx.x * 8 + warp;
    if (node >= n) return;
    float v = (lane < NF) ? nf[(size_t)node * NF + lane] : 0.f;
    for (; node < n; node += stride) {
        int nxt = node + stride;
        float vn = 0.f;
        if (nxt < n && lane < NF) vn = nf[(size_t)nxt * NF + lane];
        float a0 = sb[2 * lane], a1 = sb[2 * lane + 1];
#pragma unroll
        for (int k = 0; k < NF; k++) {
            float xv = __shfl_sync(0xffffffffu, v, k);
            a0 += xv * sW[k * 64 + 2 * lane];
            a1 += xv * sW[k * 64 + 2 * lane + 1];
        }
        float2 r;
        r.x = fmaxf(a0, 0.f);
        r.y = fmaxf(a1, 0.f);
        *reinterpret_cast<float2*>(&g_x[(size_t)node * 64 + 2 * lane]) = r;
        *reinterpret_cast<__half2*>(&g_xh[(size_t)node * 64 + 2 * lane]) =
            __floats2half2_rn(r.x, r.y);
        v = vn;
    }
}

// ---------------- k_pre_mma: PR/PC via tensor cores -------------------------
__global__ __launch_bounds__(256) void k_pre_mma(int l, int n) {
    extern __shared__ __align__(16) unsigned char smraw[];
    __half* sWb = reinterpret_cast<__half*>(smraw);                 // 192*64 halfs
    __half* sx = reinterpret_cast<__half*>(smraw + 24576);          // 128*64 halfs
    float* sbias = reinterpret_cast<float*>(smraw + 24576 + 16384); // 192 floats
    int tid = threadIdx.x;
    const uint4* gW = reinterpret_cast<const uint4*>(g_Wb + l * 12288);
    uint4* sW4 = reinterpret_cast<uint4*>(sWb);
    for (int i = tid; i < 1536; i += 256) {
        int r = i >> 3, c = i & 7;
        sW4[r * 8 + (c ^ (r & 7))] = gW[i];
    }
    for (int i = tid; i < 192; i += 256) sbias[i] = g_bias[l * 192 + i];
    uint32_t sx_u = (uint32_t)__cvta_generic_to_shared(sx);
    uint32_t sW_u = (uint32_t)__cvta_generic_to_shared(sWb);
    int warp = tid >> 5, lane = tid & 31;
    int nb = (n + 127) >> 7;

    for (int batch = blockIdx.x; batch < nb; batch += gridDim.x) {
        int base = batch << 7;
        __syncthreads();
        const uint4* gx = reinterpret_cast<const uint4*>(g_xh + (size_t)base * 64);
        uint4* sx4 = reinterpret_cast<uint4*>(sx);
        for (int i = tid; i < 1024; i += 256) {
            int r = i >> 3, c = i & 7;
            uint4 v = make_uint4(0, 0, 0, 0);
            if (base + r < n) v = gx[i];
            sx4[r * 8 + (c ^ (r & 7))] = v;
        }
        __syncthreads();

        uint32_t a[4][4];
        int m0 = warp * 16;
        {
            int grp = lane >> 3, lr = lane & 7;
            int r = m0 + ((grp & 1) << 3) + lr;
            int chalf = grp >> 1;
#pragma unroll
            for (int kb = 0; kb < 4; kb++) {
                int c = kb * 2 + chalf;
                uint32_t addr = sx_u + (uint32_t)((r * 8 + (c ^ (r & 7))) * 16);
                ldsm_x4(a[kb][0], a[kb][1], a[kb][2], a[kb][3], addr);
            }
        }
        int grp2 = (lane >> 3) & 1, lr2 = lane & 7;
        int mlo = base + m0 + (lane >> 2);
        int mhi = mlo + 8;
#pragma unroll 1
        for (int t = 0; t < 24; t++) {
            float c0 = 0.f, c1 = 0.f, c2 = 0.f, c3 = 0.f;
#pragma unroll
            for (int kb = 0; kb < 4; kb++) {
                int nrow = t * 8 + lr2;
                int cch = kb * 2 + grp2;
                uint32_t baddr =
                    sW_u + (uint32_t)((nrow * 8 + (cch ^ (nrow & 7))) * 16);
                uint32_t b0, b1;
                ldsm_x2(b0, b1, baddr);
                mma16816(c0, c1, c2, c3, a[kb][0], a[kb][1], a[kb][2], a[kb][3],
                         b0, b1);
            }
            int nloc = t * 8 + 2 * (lane & 3);
            float bsa = sbias[nloc], bsb = sbias[nloc + 1];
            c0 += bsa; c1 += bsb; c2 += bsa; c3 += bsb;
            __half* dst;
            int off;
            if (t < 8) { dst = g_PR; off = nloc; }
            else if (t < 16) { dst = g_PC; off = nloc - 64; }
            else if (t < 20) { dst = g_PR; off = nloc - 64; }
            else { dst = g_PC; off = nloc - 96; }
            if (mlo < n)
                *reinterpret_cast<__half2*>(dst + (size_t)mlo * 128 + off) =
                    __floats2half2_rn(c0, c1);
            if (mhi < n)
                *reinterpret_cast<__half2*>(dst + (size_t)mhi * 128 + off) =
                    __floats2half2_rn(c2, c3);
        }
    }
}

// ---------------- edge kernel: half-warp per edge, padded aligned rows ------
__global__ __launch_bounds__(128) void k_edge(const int* __restrict__ row,
                                              const int* __restrict__ col,
                                              const float* __restrict__ ew,
                                              const float* __restrict__ aW2,
                                              const float* __restrict__ ab2, int ne) {
    __shared__ float s_aw2[32];
    if (threadIdx.x < 32) s_aw2[threadIdx.x] = aW2[threadIdx.x];
    __syncthreads();
    int warpsPerBlk = blockDim.x >> 5;
    int W = gridDim.x * warpsPerBlk;
    int w = blockIdx.x * warpsPerBlk + (threadIdx.x >> 5);
    int hl = threadIdx.x & 15;
    int half = (threadIdx.x >> 4) & 1;
    float2 aw;
    aw.x = s_aw2[2 * hl];
    aw.y = s_aw2[2 * hl + 1];
    float ab2v = __ldg(ab2);
    int S = 2 * W;
    const __half2 z2 = __float2half2_rn(0.f);

    for (int eb = 2 * w; eb < ne; eb += 2 * S) {
        int e0 = eb + half;
        int e1 = e0 + S;
        bool v0 = e0 < ne;
        bool v1 = e1 < ne;
        int e0c = v0 ? e0 : 0;
        int e1c = v1 ? e1 : 0;
        int r0 = row[e0c], c0 = col[e0c];
        int r1 = row[e1c], c1 = col[e1c];
        float w0 = ew[e0c], w1 = ew[e1c];

        const __half* pr0 = g_PR + (size_t)r0 * 128;
        const __half* pc0 = g_PC + (size_t)c0 * 128;
        const __half* pr1 = g_PR + (size_t)r1 * 128;
        const __half* pc1 = g_PC + (size_t)c1 * 128;

        uint2 pm0r = __ldg(reinterpret_cast<const uint2*>(pr0 + 4 * hl));
        uint2 pm0c = __ldg(reinterpret_cast<const uint2*>(pc0 + 4 * hl));
        uint2 pm1r = __ldg(reinterpret_cast<const uint2*>(pr1 + 4 * hl));
        uint2 pm1c = __ldg(reinterpret_cast<const uint2*>(pc1 + 4 * hl));
        __half2 pa0r = __ldg(reinterpret_cast<const __half2*>(pr0 + 64 + 2 * hl));
        __half2 pa0c = __ldg(reinterpret_cast<const __half2*>(pc0 + 64 + 2 * hl));
        __half2 pa1r = __ldg(reinterpret_cast<const __half2*>(pr1 + 64 + 2 * hl));
        __half2 pa1c = __ldg(reinterpret_cast<const __half2*>(pc1 + 64 + 2 * hl));

        float2 a0f = __half22float2(__hmax2(__hadd2(pa0r, pa0c), z2));
        float2 a1f = __half22float2(__hmax2(__hadd2(pa1r, pa1c), z2));
        float t0 = a0f.x * aw.x + a0f.y * aw.y;
        float t1 = a1f.x * aw.x + a1f.y * aw.y;
#pragma unroll
        for (int o = 8; o > 0; o >>= 1) {
            t0 += __shfl_xor_sync(0xffffffffu, t0, o);
            t1 += __shfl_xor_sync(0xffffffffu, t1, o);
        }
        float fw0 = w0 / (1.f + __expf(-(t0 + ab2v)));
        float fw1 = w1 / (1.f + __expf(-(t1 + ab2v)));

        float2 f00 = __half22float2(__hmax2(__hadd2(u32_as_half2(pm0r.x), u32_as_half2(pm0c.x)), z2));
        float2 f01 = __half22float2(__hmax2(__hadd2(u32_as_half2(pm0r.y), u32_as_half2(pm0c.y)), z2));
        float2 f10 = __half22float2(__hmax2(__hadd2(u32_as_half2(pm1r.x), u32_as_half2(pm1c.x)), z2));
        float2 f11 = __half22float2(__hmax2(__hadd2(u32_as_half2(pm1r.y), u32_as_half2(pm1c.y)), z2));

        if (v0) {
            float* d0 = &g_S[(size_t)c0 * 64 + 4 * hl];
            asm volatile("red.global.add.v4.f32 [%0], {%1,%2,%3,%4};" ::"l"(d0),
                         "f"(f00.x * fw0), "f"(f00.y * fw0), "f"(f01.x * fw0),
                         "f"(f01.y * fw0)
                         : "memory");
            if (hl == 0) atomicAdd(&g_sumfw[c0], fw0);
        }
        if (v1) {
            float* d1 = &g_S[(size_t)c1 * 64 + 4 * hl];
            asm volatile("red.global.add.v4.f32 [%0], {%1,%2,%3,%4};" ::"l"(d1),
                         "f"(f10.x * fw1), "f"(f10.y * fw1), "f"(f11.x * fw1),
                         "f"(f11.y * fw1)
                         : "memory");
            if (hl == 0) atomicAdd(&g_sumfw[c1], fw1);
        }
    }
}

// ---------------- k_update_mma: tensor-core fused update (rezero fused) -----
// h = relu(b1 + inv*(S@Wc) + (sf*inv)*bvec + X@U1a); o = relu(h@U2 + b2 + x)
__global__ __launch_bounds__(256) void k_update_mma(int l,
                                                    const float* __restrict__ ub1,
                                                    const float* __restrict__ ub2,
                                                    int n, int do_max) {
    extern __shared__ __align__(16) unsigned char smraw[];
    __half* sW = reinterpret_cast<__half*>(smraw);          // 3*4096 halfs (24576B)
    __half* sx = reinterpret_cast<__half*>(smraw + 24576);  // 8192 halfs (16384B)
    __half* sh = reinterpret_cast<__half*>(smraw + 40960);  // S then H (16384B)
    float* sb = reinterpret_cast<float*>(smraw + 57344);    // 192: b1|b2|bvec
    float* ssf = sb + 192;                                  // 128
    unsigned* smx = reinterpret_cast<unsigned*>(ssf + 128); // 64
    int tid = threadIdx.x;

    {
        const uint4* gW = reinterpret_cast<const uint4*>(g_Wu + l * 12288);
        uint4* sW4 = reinterpret_cast<uint4*>(sW);
        for (int i = tid; i < 1536; i += 256) {
            int r = i >> 3, c = i & 7;
            sW4[r * 8 + (c ^ (r & 7))] = gW[i];
        }
        if (tid < 64) {
            sb[tid] = ub1[tid];
            sb[64 + tid] = ub2[tid];
            sb[128 + tid] = g_bvec[l * 64 + tid];
            smx[tid] = 0u;
        }
    }
    uint32_t sx_u = (uint32_t)__cvta_generic_to_shared(sx);
    uint32_t sh_u = (uint32_t)__cvta_generic_to_shared(sh);
    uint32_t sW_u = (uint32_t)__cvta_generic_to_shared(sW);
    int warp = tid >> 5, lane = tid & 31;
    int m0 = warp * 16;
    int grp = lane >> 3, lr = lane & 7;
    int afr = m0 + ((grp & 1) << 3) + lr;
    int achalf = grp >> 1;
    int grp2 = (lane >> 3) & 1, lr2 = lane & 7;
    int rlo = m0 + (lane >> 2), rhi = rlo + 8;
    int nb = (n + 127) >> 7;
    float mxa[8], mxb[8];
#pragma unroll
    for (int t = 0; t < 8; t++) { mxa[t] = 0.f; mxb[t] = 0.f; }
    float4 z4 = make_float4(0.f, 0.f, 0.f, 0.f);

    for (int batch = blockIdx.x; batch < nb; batch += gridDim.x) {
        int base = batch << 7;
        __syncthreads();
        {
            const uint4* gx = reinterpret_cast<const uint4*>(g_xh + (size_t)base * 64);
            uint4* sx4 = reinterpret_cast<uint4*>(sx);
            uint4* sh4 = reinterpret_cast<uint4*>(sh);
            float4* gs4 = reinterpret_cast<float4*>(g_S + (size_t)base * 64);
            for (int i = tid; i < 1024; i += 256) {
                int r = i >> 3;
                uint4 vx = make_uint4(0, 0, 0, 0);
                uint4 vs = make_uint4(0, 0, 0, 0);
                if (base + r < n) {
                    vx = gx[i];
                    float4 f0 = gs4[2 * i];
                    float4 f1 = gs4[2 * i + 1];
                    gs4[2 * i] = z4;          // rezero for next layer / replay
                    gs4[2 * i + 1] = z4;
                    __half2 h0 = __floats2half2_rn(f0.x, f0.y);
                    __half2 h1 = __floats2half2_rn(f0.z, f0.w);
                    __half2 h2 = __floats2half2_rn(f1.x, f1.y);
                    __half2 h3 = __floats2half2_rn(f1.z, f1.w);
                    vs.x = *reinterpret_cast<unsigned*>(&h0);
                    vs.y = *reinterpret_cast<unsigned*>(&h1);
                    vs.z = *reinterpret_cast<unsigned*>(&h2);
                    vs.w = *reinterpret_cast<unsigned*>(&h3);
                }
                int d = (i >> 3) * 8 + ((i & 7) ^ ((i >> 3) & 7));
                sx4[d] = vx;
                sh4[d] = vs;
            }
            if (tid < 128) {
                float sf = 1.f;
                if (base + tid < n) {
                    sf = g_sumfw[base + tid];
                    g_sumfw[base + tid] = 0.f;
                }
                ssf[tid] = sf;
            }
        }
        __syncthreads();

        uint32_t aS[4][4], aX[4][4];
#pragma unroll
        for (int kb = 0; kb < 4; kb++) {
            int c = kb * 2 + achalf;
            uint32_t off = (uint32_t)((afr * 8 + (c ^ (afr & 7))) * 16);
            ldsm_x4(aS[kb][0], aS[kb][1], aS[kb][2], aS[kb][3], sh_u + off);
            ldsm_x4(aX[kb][0], aX[kb][1], aX[kb][2], aX[kb][3], sx_u + off);
        }
        float sflo = ssf[rlo], sfhi = ssf[rhi];
        float invlo = 1.f / fmaxf(sflo, 1e-6f);
        float invhi = 1.f / fmaxf(sfhi, 1e-6f);
        float ratlo = sflo * invlo, rathi = sfhi * invhi;

#pragma unroll 1
        for (int t = 0; t < 8; t++) {
            float g0 = 0.f, g1 = 0.f, g2 = 0.f, g3 = 0.f;
            float h0 = 0.f, h1 = 0.f, h2 = 0.f, h3 = 0.f;
            int nrow = t * 8 + lr2;
#pragma unroll
            for (int kb = 0; kb < 4; kb++) {
                int cch = kb * 2 + grp2;
                uint32_t off = (uint32_t)((nrow * 8 + (cch ^ (nrow & 7))) * 16);
                uint32_t b0, b1;
                ldsm_x2(b0, b1, sW_u + off);
                mma16816(g0, g1, g2, g3, aS[kb][0], aS[kb][1], aS[kb][2], aS[kb][3], b0, b1);
                ldsm_x2(b0, b1, sW_u + 8192u + off);
                mma16816(h0, h1, h2, h3, aX[kb][0], aX[kb][1], aX[kb][2], aX[kb][3], b0, b1);
            }
            int nloc = t * 8 + 2 * (lane & 3);
            float b1a = sb[nloc], b1b = sb[nloc + 1];
            float bva = sb[128 + nloc], bvb = sb[128 + nloc + 1];
            float v0 = fmaxf(b1a + invlo * g0 + ratlo * bva + h0, 0.f);
            float v1 = fmaxf(b1b + invlo * g1 + ratlo * bvb + h1, 0.f);
            float v2 = fmaxf(b1a + invhi * g2 + rathi * bva + h2, 0.f);
            float v3 = fmaxf(b1b + invhi * g3 + rathi * bvb + h3, 0.f);
            *reinterpret_cast<__half2*>(
                sh + (size_t)((rlo * 8 + (t ^ (rlo & 7))) * 8 + 2 * (lane & 3))) =
                __floats2half2_rn(v0, v1);
            *reinterpret_cast<__half2*>(
                sh + (size_t)((rhi * 8 + (t ^ (rhi & 7))) * 8 + 2 * (lane & 3))) =
                __floats2half2_rn(v2, v3);
        }
        __syncwarp();

#pragma unroll
        for (int kb = 0; kb < 4; kb++) {
            int c = kb * 2 + achalf;
            uint32_t off = (uint32_t)((afr * 8 + (c ^ (afr & 7))) * 16);
            ldsm_x4(aS[kb][0], aS[kb][1], aS[kb][2], aS[kb][3], sh_u + off);
        }

        bool vlo = (base + rlo) < n, vhi = (base + rhi) < n;
#pragma unroll 1
        for (int t = 0; t < 8; t++) {
            float o0 = 0.f, o1 = 0.f, o2 = 0.f, o3 = 0.f;
            int nrow = t * 8 + lr2;
#pragma unroll
            for (int kb = 0; kb < 4; kb++) {
                int cch = kb * 2 + grp2;
                uint32_t off = (uint32_t)((nrow * 8 + (cch ^ (nrow & 7))) * 16);
                uint32_t b0, b1;
                ldsm_x2(b0, b1, sW_u + 16384u + off);
                mma16816(o0, o1, o2, o3, aS[kb][0], aS[kb][1], aS[kb][2], aS[kb][3], b0, b1);
            }
            int nloc = t * 8 + 2 * (lane & 3);
            float b2a = sb[64 + nloc], b2b = sb[64 + nloc + 1];
            float2 xlo = __half22float2(*reinterpret_cast<const __half2*>(
                sx + (size_t)((rlo * 8 + (t ^ (rlo & 7))) * 8 + 2 * (lane & 3))));
            float2 xhi = __half22float2(*reinterpret_cast<const __half2*>(
                sx + (size_t)((rhi * 8 + (t ^ (rhi & 7))) * 8 + 2 * (lane & 3))));
            float r0 = fmaxf(o0 + b2a + xlo.x, 0.f);
            float r1 = fmaxf(o1 + b2b + xlo.y, 0.f);
            float r2 = fmaxf(o2 + b2a + xhi.x, 0.f);
            float r3 = fmaxf(o3 + b2b + xhi.y, 0.f);
            if (vlo) {
                float2 t2; t2.x = r0; t2.y = r1;
                *reinterpret_cast<float2*>(&g_x[(size_t)(base + rlo) * 64 + nloc]) = t2;
                *reinterpret_cast<__half2*>(&g_xh[(size_t)(base + rlo) * 64 + nloc]) =
                    __floats2half2_rn(r0, r1);
                mxa[t] = fmaxf(mxa[t], r0);
                mxb[t] = fmaxf(mxb[t], r1);
            }
            if (vhi) {
                float2 t2; t2.x = r2; t2.y = r3;
                *reinterpret_cast<float2*>(&g_x[(size_t)(base + rhi) * 64 + nloc]) = t2;
                *reinterpret_cast<__half2*>(&g_xh[(size_t)(base + rhi) * 64 + nloc]) =
                    __floats2half2_rn(r2, r3);
                mxa[t] = fmaxf(mxa[t], r2);
                mxb[t] = fmaxf(mxb[t], r3);
            }
        }
    }

    if (do_max) {
        __syncthreads();
#pragma unroll
        for (int t = 0; t < 8; t++) {
            int nloc = t * 8 + 2 * (lane & 3);
            atomicMax(&smx[nloc], __float_as_uint(mxa[t]));
            atomicMax(&smx[nloc + 1], __float_as_uint(mxb[t]));
        }
        __syncthreads();
        if (tid < 64)
            atomicMax(reinterpret_cast<unsigned*>(&g_mx[tid]), smx[tid]);
    }
}

// ---------------- head: out = max_x @ head_W + head_b -----------------------
__global__ void k_head(const float* __restrict__ hW, const float* __restrict__ hb,
                       float* __restrict__ out) {
    int t = threadIdx.x;
    float v = g_mx[t] * hW[t];
#pragma unroll
    for (int o = 16; o > 0; o >>= 1) v += __shfl_xor_sync(0xffffffffu, v, o);
    __shared__ float s[2];
    if ((t & 31) == 0) s[t >> 5] = v;
    __syncthreads();
    if (t == 0) out[0] = s[0] + s[1] + hb[0];
}

// ---------------- launch ----------------------------------------------------
extern "C" void kernel_launch(void* const* d_in, const int* in_sizes, int n_in,
                              void* d_out, int out_size) {
    const float* nf = (const float*)d_in[0];
    const int* ei = (const int*)d_in[1];
    const float* ew = (const float*)d_in[2];
    const float* embW = (const float*)d_in[3];
    const float* embB = (const float*)d_in[4];
    const float* msgW1 = (const float*)d_in[5];
    const float* msgB1 = (const float*)d_in[6];
    const float* msgW2 = (const float*)d_in[7];
    const float* msgB2 = (const float*)d_in[8];
    const float* attW1 = (const float*)d_in[9];
    const float* attB1 = (const float*)d_in[10];
    const float* attW2 = (const float*)d_in[11];
    const float* attB2 = (const float*)d_in[12];
    const float* updW1 = (const float*)d_in[13];
    const float* updB1 = (const float*)d_in[14];
    const float* updW2 = (const float*)d_in[15];
    const float* updB2 = (const float*)d_in[16];
    const float* headW = (const float*)d_in[17];
    const float* headB = (const float*)d_in[18];
    float* out = (float*)d_out;

    int n = in_sizes[0] / NF;
    int ne = in_sizes[2];
    const int* row = ei;
    const int* col = ei + ne;

    cudaFuncSetAttribute(k_pre_mma, cudaFuncAttributeMaxDynamicSharedMemorySize, 41728);
    cudaFuncSetAttribute(k_update_mma, cudaFuncAttributeMaxDynamicSharedMemorySize, 59904);

    k_wprep<<<2, 256>>>(msgW1, attW1, msgB1, attB1);
    k_fuse<<<dim3(2, 8), 256>>>(msgW2, msgB2, updW1);
    k_wprep2<<<2, 256>>>(updW1, updW2);
    k_embed<<<1184, 256>>>(nf, embW, embB, n);
    for (int l = 0; l < 2; l++) {
        k_pre_mma<<<784, 256, 41728>>>(l, n);
        k_edge<<<2368, 128>>>(row, col, ew, attW2 + l * 32, attB2 + l, ne);
        k_update_mma<<<444, 256, 59904>>>(l, updB1 + l * 64, updB2 + l * 64, n,
                                          (l == 1) ? 1 : 0);
    }
    k_head<<<1, 64>>>(headW, headB, out);
}